// round 8
// baseline (speedup 1.0000x reference)
#include <cuda_runtime.h>
#include <math.h>
#include <stdint.h>

#define M_    8
#define B_    64
#define S_    128
#define D_    512
#define H_    8
#define HD_   64
#define FF_   1024
#define MH_   64
#define TWOD_ 1024

typedef unsigned long long u64;

// ---------------- scratch ----------------
__device__ float g_q [M_*B_*D_];
__device__ float g_qk[B_*MH_*D_];
__device__ float g_w [B_*MH_*S_];
__device__ float g_wv[B_*MH_*D_];
__device__ float g_ao[M_*B_*D_];
__device__ float g_x [M_*B_*TWOD_];
__device__ float g_h [4*M_*B_*FF_];
__device__ float g_hg[4*M_*B_*FF_];
__device__ float g_o [4*M_*B_*D_];

// ---------------- packed f32x2 helpers ----------------
__device__ __forceinline__ void upk2(float& x, float& y, u64 p) {
    asm("mov.b64 {%0,%1}, %2;" : "=f"(x), "=f"(y) : "l"(p));
}
__device__ __forceinline__ void ffma2(u64& d, u64 a, u64 b) {
    asm("fma.rn.f32x2 %0, %1, %2, %0;" : "+l"(d) : "l"(a), "l"(b));
}

// ============ packed GEMM: C[b][n] = epi(sum_k X[b][k]*W[k][n] + bias[n]) ============
// 64 batch x NF features per CTA, 256 thr. Warps 2(b)x4(f); thread tile 8b x F feat.
// A duplicated in smem -> (a,a) pairs via plain 16B loads; acc paired over adjacent
// features -> (b0,b1) pairs native from Bs. Zero packing MOVs in the inner loop.
template<int NF, int EPI>
__device__ __forceinline__ void pgemm(const float* __restrict__ X, int ldx,
                                      const float* __restrict__ W, int ldw,
                                      float* __restrict__ C, int ldc,
                                      const float* __restrict__ bi, int K)
{
    constexpr int F  = NF / 32;      // per-thread features (8 or 4)
    constexpr int FP = F / 2;        // feature pairs
    __shared__ __align__(16) float As[16][136];   // [k][2b] duplicated, padded
    __shared__ __align__(16) float Bs[16][NF];

    const int tid = threadIdx.x, lane = tid & 31, warp = tid >> 5;
    const int wb = warp >> 2, wf = warp & 3;
    const int tb = lane & 3,  tf = lane >> 2;
    const int b8 = wb * 32 + tb * 8;
    const int f0 = wf * (NF / 4) + tf * F;

    const int la_b = tid >> 2;             // A loader batch row
    const int la_k = (tid & 3) << 2;       // A loader k quad

    u64 acc[8][FP];
    #pragma unroll
    for (int i = 0; i < 8; i++)
        #pragma unroll
        for (int j = 0; j < FP; j++) acc[i][j] = 0ull;

    for (int k0 = 0; k0 < K; k0 += 16) {
        if (k0) __syncthreads();
        {   // A: duplicated transpose  As[k][2b]=As[k][2b+1]=X[b][k]
            float4 xa = *(const float4*)(X + (long long)la_b * ldx + k0 + la_k);
            *(float2*)&As[la_k + 0][2 * la_b] = make_float2(xa.x, xa.x);
            *(float2*)&As[la_k + 1][2 * la_b] = make_float2(xa.y, xa.y);
            *(float2*)&As[la_k + 2][2 * la_b] = make_float2(xa.z, xa.z);
            *(float2*)&As[la_k + 3][2 * la_b] = make_float2(xa.w, xa.w);
        }
        #pragma unroll
        for (int j = 0; j < NF / 64; j++) {   // B direct, coalesced
            int fidx = tid + j * 256;
            int r = fidx / (NF / 4), c4 = fidx % (NF / 4);
            *(float4*)&Bs[r][c4 * 4] =
                *(const float4*)(W + (long long)(k0 + r) * ldw + c4 * 4);
        }
        __syncthreads();

        #pragma unroll
        for (int kk = 0; kk < 16; kk++) {
            u64 au[8];
            {
                const ulonglong2* ap = (const ulonglong2*)&As[kk][2 * b8];
                ulonglong2 p0 = ap[0], p1 = ap[1], p2 = ap[2], p3 = ap[3];
                au[0] = p0.x; au[1] = p0.y; au[2] = p1.x; au[3] = p1.y;
                au[4] = p2.x; au[5] = p2.y; au[6] = p3.x; au[7] = p3.y;
            }
            u64 bu[FP];
            {
                const ulonglong2* bp = (const ulonglong2*)&Bs[kk][f0];
                ulonglong2 q0 = bp[0];
                bu[0] = q0.x; bu[1] = q0.y;
                if (FP == 4) { ulonglong2 q1 = bp[1]; bu[2] = q1.x; bu[3] = q1.y; }
            }
            #pragma unroll
            for (int i = 0; i < 8; i++)
                #pragma unroll
                for (int j = 0; j < FP; j++)
                    ffma2(acc[i][j], au[i], bu[j]);
        }
    }

    #pragma unroll
    for (int i = 0; i < 8; i++) {
        float v[F];
        #pragma unroll
        for (int j = 0; j < FP; j++) {
            float lo, hi; upk2(lo, hi, acc[i][j]);
            lo += bi[f0 + 2 * j]; hi += bi[f0 + 2 * j + 1];
            if (EPI >= 1) { lo = fmaxf(lo, 0.0f); hi = fmaxf(hi, 0.0f); }
            if (EPI == 2) { lo = tanhf(lo); hi = tanhf(hi); }
            v[2 * j] = lo; v[2 * j + 1] = hi;
        }
        float* r0 = C + (long long)(b8 + i) * ldc + f0;
        #pragma unroll
        for (int j4 = 0; j4 < F; j4 += 4)
            *(float4*)(r0 + j4) = make_float4(v[j4], v[j4+1], v[j4+2], v[j4+3]);
    }
}

// mlp1 (W1 & Wg1 fused in one grid): z 0..63
__global__ void __launch_bounds__(256) k_mlp1(const float* __restrict__ W1,
                                              const float* __restrict__ b1,
                                              const float* __restrict__ Wg1,
                                              const float* __restrict__ bg1)
{
    int z = blockIdx.z, zz = z & 31, m = zz & 7, bx = blockIdx.x;
    const float* W = (z < 32 ? W1 : Wg1) + (long long)zz * TWOD_ * FF_ + bx * 256;
    const float* bi = (z < 32 ? b1 : bg1) + (long long)zz * FF_ + bx * 256;
    float* C = (z < 32 ? g_h : g_hg) + (long long)zz * B_ * FF_ + bx * 256;
    pgemm<256, 1>(g_x + (long long)m * B_ * TWOD_, TWOD_, W, FF_, C, FF_, bi, TWOD_);
}

// mlp2: z 0..31
__global__ void __launch_bounds__(256) k_mlp2(const float* __restrict__ W2,
                                              const float* __restrict__ b2)
{
    int z = blockIdx.z, bx = blockIdx.x;
    pgemm<128, 2>(g_h + (long long)z * B_ * FF_, FF_,
                  W2 + (long long)z * FF_ * D_ + bx * 128, D_,
                  g_o + (long long)z * B_ * D_ + bx * 128, D_,
                  b2 + (long long)z * D_ + bx * 128, FF_);
}

// ---------------- SIMT 64x64 GEMM core, FFMA2 version ----------------
template<bool TB, int EPI>
__device__ __forceinline__ void gemm64(const float* __restrict__ A, int lda,
                                       const float* __restrict__ Bp, int ldb,
                                       float* __restrict__ C, int ldc,
                                       int K, const float* __restrict__ bias)
{
    __shared__ __align__(16) float As[16][132];   // duplicated rows
    __shared__ __align__(16) float Bs[16][64];
    const int tid = threadIdx.x;
    const int tx = tid & 15, ty = tid >> 4;
    const int ar = tid >> 2, ak = (tid & 3) << 2;
    const int nk = tid >> 4, nc = (tid & 15) << 2;

    u64 acc[4][2] = {};

    for (int k0 = 0; k0 < K; k0 += 16) {
        __syncthreads();
        {
            float4 av = *(const float4*)(A + ar * lda + k0 + ak);
            *(float2*)&As[ak + 0][2 * ar] = make_float2(av.x, av.x);
            *(float2*)&As[ak + 1][2 * ar] = make_float2(av.y, av.y);
            *(float2*)&As[ak + 2][2 * ar] = make_float2(av.z, av.z);
            *(float2*)&As[ak + 3][2 * ar] = make_float2(av.w, av.w);
        }
        if (TB) {
            float4 bv = *(const float4*)(Bp + ar * ldb + k0 + ak);
            Bs[ak + 0][ar] = bv.x; Bs[ak + 1][ar] = bv.y;
            Bs[ak + 2][ar] = bv.z; Bs[ak + 3][ar] = bv.w;
        } else {
            *(float4*)&Bs[nk][nc] = *(const float4*)(Bp + (k0 + nk) * ldb + nc);
        }
        __syncthreads();
        #pragma unroll
        for (int kk = 0; kk < 16; kk++) {
            const ulonglong2* ap = (const ulonglong2*)&As[kk][ty << 3];
            ulonglong2 p0 = ap[0], p1 = ap[1];
            u64 au[4] = {p0.x, p0.y, p1.x, p1.y};
            ulonglong2 q = *(const ulonglong2*)&Bs[kk][tx << 2];
            u64 bu[2] = {q.x, q.y};
            #pragma unroll
            for (int i = 0; i < 4; i++)
                #pragma unroll
                for (int j = 0; j < 2; j++)
                    ffma2(acc[i][j], au[i], bu[j]);
        }
    }
    #pragma unroll
    for (int i = 0; i < 4; i++) {
        int r = (ty << 2) + i;
        #pragma unroll
        for (int j = 0; j < 2; j++) {
            int c = (tx << 2) + 2 * j;
            float lo, hi; upk2(lo, hi, acc[i][j]);
            if (bias) { lo += bias[c]; hi += bias[c + 1]; }
            if (EPI >= 1) { lo = fmaxf(lo, 0.0f); hi = fmaxf(hi, 0.0f); }
            C[r * ldc + c] = lo;
            C[r * ldc + c + 1] = hi;
        }
    }
}

__global__ void __launch_bounds__(256) k_qproj(const float* __restrict__ pq,
                                               const float* __restrict__ Wq,
                                               const float* __restrict__ bq)
{
    int m = blockIdx.z, n0 = blockIdx.x * 64;
    gemm64<false, 0>(pq + m * B_ * D_, D_,
                     Wq + m * D_ * D_ + n0, D_,
                     g_q + m * B_ * D_ + n0, D_, D_, bq + m * D_ + n0);
}

__global__ void __launch_bounds__(256) k_qk(const float* __restrict__ Wk)
{
    int m = blockIdx.z >> 3, h = blockIdx.z & 7, n0 = blockIdx.x * 64;
    gemm64<true, 0>(g_q + m * B_ * D_ + h * HD_, D_,
                    Wk + m * D_ * D_ + n0 * D_ + h * HD_, D_,
                    g_qk + (m * H_ + h) * D_ + n0, MH_ * D_, HD_, nullptr);
}

__global__ void __launch_bounds__(256) k_scores(const float* __restrict__ key_in)
{
    int b = blockIdx.z, n0 = blockIdx.x * 64;
    gemm64<true, 0>(g_qk + b * MH_ * D_, D_,
                    key_in + (long)n0 * B_ * D_ + b * D_, B_ * D_,
                    g_w + b * MH_ * S_ + n0, S_, D_, nullptr);
}

__global__ void __launch_bounds__(256) k_softmax(const float* __restrict__ bk)
{
    int row = blockIdx.x * 8 + (threadIdx.x >> 5);
    int lane = threadIdx.x & 31;
    int b = row >> 6, mh = row & 63;
    int m = mh >> 3, h = mh & 7;
    const float* qp  = g_q + m * B_ * D_ + b * D_ + h * HD_;
    const float* bkp = bk + m * D_ + h * HD_;
    float bias = qp[lane] * bkp[lane] + qp[lane + 32] * bkp[lane + 32];
    #pragma unroll
    for (int o = 16; o; o >>= 1) bias += __shfl_xor_sync(0xffffffffu, bias, o);
    float* wrow = g_w + b * MH_ * S_ + mh * S_;
    float v[4], mx = -INFINITY;
    #pragma unroll
    for (int i = 0; i < 4; i++) {
        v[i] = (wrow[lane + 32 * i] + bias) * 0.125f;
        mx = fmaxf(mx, v[i]);
    }
    #pragma unroll
    for (int o = 16; o; o >>= 1) mx = fmaxf(mx, __shfl_xor_sync(0xffffffffu, mx, o));
    float sum = 0.0f;
    #pragma unroll
    for (int i = 0; i < 4; i++) { v[i] = __expf(v[i] - mx); sum += v[i]; }
    #pragma unroll
    for (int o = 16; o; o >>= 1) sum += __shfl_xor_sync(0xffffffffu, sum, o);
    float inv = 1.0f / sum;
    #pragma unroll
    for (int i = 0; i < 4; i++) wrow[lane + 32 * i] = v[i] * inv;
}

__global__ void __launch_bounds__(256) k_wv(const float* __restrict__ value_in)
{
    int b = blockIdx.z, n0 = blockIdx.x * 64;
    gemm64<false, 0>(g_w + b * MH_ * S_, S_,
                     value_in + b * D_ + n0, B_ * D_,
                     g_wv + b * MH_ * D_ + n0, D_, S_, nullptr);
}

__global__ void __launch_bounds__(256) k_ao(const float* __restrict__ Wv,
                                            const float* __restrict__ bv)
{
    int m = blockIdx.z >> 3, h = blockIdx.z & 7;
    gemm64<false, 0>(g_wv + (m * H_ + h) * D_, MH_ * D_,
                     Wv + m * D_ * D_ + h * HD_, D_,
                     g_ao + m * B_ * D_ + h * HD_, D_, D_, bv + m * D_ + h * HD_);
}

__global__ void __launch_bounds__(256) k_attnout(const float* __restrict__ Wo,
                                                 const float* __restrict__ bo)
{
    int m = blockIdx.z, n0 = blockIdx.x * 64;
    gemm64<false, 1>(g_ao + m * B_ * D_, D_,
                     Wo + m * D_ * D_ + n0, D_,
                     g_x + m * B_ * TWOD_ + n0, TWOD_, D_, bo + m * D_ + n0);
}

__global__ void __launch_bounds__(256) k_xfill(const float* __restrict__ ps)
{
    int i = blockIdx.x * 256 + threadIdx.x;
    if (i < M_ * B_ * D_) {
        int mb = i >> 9, d = i & (D_ - 1);
        g_x[mb * TWOD_ + D_ + d] = fmaxf(ps[i], 0.0f);
    }
}

__global__ void __launch_bounds__(128) k_final(const float* __restrict__ Wg2,
                                               const float* __restrict__ bg2,
                                               const float* __restrict__ pq,
                                               const float* __restrict__ pk,
                                               const float* __restrict__ pv,
                                               const float* __restrict__ ps,
                                               float* __restrict__ out)
{
    int z = blockIdx.x;
    int g = z >> 9, rem = z & 511;
    int m = rem >> 6, b = rem & 63;
    int gm = g * M_ + m;
    int tid = threadIdx.x, lane = tid & 31;
    const float* hg = g_hg + ((long)gm * B_ + b) * FF_;
    const float* wg = Wg2 + (long)gm * FF_;
    float s = 0.0f;
    for (int f = tid; f < FF_; f += 128) s += hg[f] * wg[f];
    #pragma unroll
    for (int o = 16; o; o >>= 1) s += __shfl_xor_sync(0xffffffffu, s, o);
    __shared__ float red[4];
    if (lane == 0) red[tid >> 5] = s;
    __syncthreads();
    float tot = red[0] + red[1] + red[2] + red[3];
    float gate = 1.0f / (1.0f + __expf(-(tot + bg2[gm])));
    const float* prevs[4] = {pq, pk, pv, ps};
    const float* pr = prevs[g] + ((long)m * B_ + b) * D_;
    const float* ob = g_o + ((long)gm * B_ + b) * D_;
    float* dst = out + (((long)((g + 1) & 3) * M_ + m) * B_ + b) * D_;
    for (int d = tid; d < D_; d += 128)
        dst[d] = gate * ob[d] + (1.0f - gate) * pr[d];
}

// ---------------- launch ----------------
extern "C" void kernel_launch(void* const* d_in, const int* in_sizes, int n_in,
                              void* d_out, int out_size)
{
    const float* prev_state = (const float*)d_in[0];
    const float* prev_query = (const float*)d_in[1];
    const float* prev_key   = (const float*)d_in[2];
    const float* prev_value = (const float*)d_in[3];
    const float* key_in     = (const float*)d_in[4];
    const float* value_in   = (const float*)d_in[5];
    const float* Wq  = (const float*)d_in[6];
    const float* bq  = (const float*)d_in[7];
    const float* Wk  = (const float*)d_in[8];
    const float* bk  = (const float*)d_in[9];
    const float* Wv  = (const float*)d_in[10];
    const float* bv  = (const float*)d_in[11];
    const float* Wo  = (const float*)d_in[12];
    const float* bo  = (const float*)d_in[13];
    const float* W1  = (const float*)d_in[14];
    const float* b1  = (const float*)d_in[15];
    const float* W2  = (const float*)d_in[16];
    const float* b2  = (const float*)d_in[17];
    const float* Wg1 = (const float*)d_in[18];
    const float* bg1 = (const float*)d_in[19];
    const float* Wg2 = (const float*)d_in[20];
    const float* bg2 = (const float*)d_in[21];
    float* out = (float*)d_out;

    k_qproj  <<<dim3(D_ / 64, 1, M_),      256>>>(prev_query, Wq, bq);
    k_qk     <<<dim3(D_ / 64, 1, M_ * H_), 256>>>(Wk);
    k_scores <<<dim3(S_ / 64, 1, B_),      256>>>(key_in);
    k_softmax<<<(B_ * MH_) / 8,            256>>>(bk);
    k_wv     <<<dim3(D_ / 64, 1, B_),      256>>>(value_in);
    k_ao     <<<dim3(1, 1, M_ * H_),       256>>>(Wv, bv);
    k_attnout<<<dim3(D_ / 64, 1, M_),      256>>>(Wo, bo);
    k_xfill  <<<(M_ * B_ * D_ + 255) / 256, 256>>>(prev_state);
    k_mlp1   <<<dim3(FF_ / 256, 1, 64),    256>>>(W1, b1, Wg1, bg1);
    k_mlp2   <<<dim3(D_ / 128, 1, 32),     256>>>(W2, b2);
    k_final  <<<4 * M_ * B_, 128>>>(Wg2, bg2, prev_query, prev_key,
                                    prev_value, prev_state, out);
}

// round 15
// speedup vs baseline: 2.2666x; 2.2666x over previous
#include <cuda_runtime.h>
#include <cuda_fp16.h>
#include <math.h>
#include <stdint.h>

#define M_    8
#define B_    64
#define S_    128
#define D_    512
#define H_    8
#define HD_   64
#define FF_   1024
#define MH_   64
#define TWOD_ 1024

// ---------------- scratch ----------------
__device__ float g_q [M_*B_*D_];
__device__ float g_qk[B_*MH_*D_];
__device__ float g_w [B_*MH_*S_];
__device__ float g_wv[B_*MH_*D_];
__device__ float g_ao[M_*B_*D_];
__device__ float g_x [M_*B_*TWOD_];
__device__ float g_h [4*M_*B_*FF_];
__device__ float g_hg[4*M_*B_*FF_];
__device__ float g_o [4*M_*B_*D_];

__device__ __forceinline__ uint32_t pkh2(float a, float b) {
    __half2 h = __floats2half2_rn(a, b);
    return *reinterpret_cast<uint32_t*>(&h);
}

// ================= fp16 mma.sync GEMM =================
// C[b][n] = epi(sum_k X[b][k] * W[k][n] + bias[n]),  f32 in/out, fp16 mma, f32 acc.
// CTA tile: 64 batch (mma M) x 128 features (mma N); 8 warps = 2(b) x 4(n), warp 32x32.
// Smem: Xh[64][40] halves (k-contig), Ws[128][40] halves = W^T (k-contig per n).
// KPW=20 words/row (80 B): 16B-aligned rows AND conflict-free fragment loads.
#define KPW 20

__device__ __forceinline__ void mma16816(float& c0, float& c1, float& c2, float& c3,
                                         uint32_t a0, uint32_t a1, uint32_t a2, uint32_t a3,
                                         uint32_t b0, uint32_t b1) {
    asm volatile("mma.sync.aligned.m16n8k16.row.col.f32.f16.f16.f32 "
                 "{%0,%1,%2,%3}, {%4,%5,%6,%7}, {%8,%9}, {%0,%1,%2,%3};"
                 : "+f"(c0), "+f"(c1), "+f"(c2), "+f"(c3)
                 : "r"(a0), "r"(a1), "r"(a2), "r"(a3), "r"(b0), "r"(b1));
}

template<int EPI>
__device__ __forceinline__ void hgemm(const float* __restrict__ X, int ldx,
                                      const float* __restrict__ W, int ldw,
                                      float* __restrict__ C, int ldc,
                                      const float* __restrict__ bi, int K)
{
    __shared__ __align__(16) uint32_t Xh[64 * KPW];    // [b][kw]
    __shared__ __align__(16) uint32_t Ws[128 * KPW];   // [n][kw]

    const int tid = threadIdx.x, lane = tid & 31, warp = tid >> 5;
    const int wb = warp >> 2, wn = warp & 3;
    const int bw = wb * 32, nw = wn * 32;
    const int gid = lane >> 2, t4 = lane & 3;

    // loader mappings
    const int xb = tid >> 2, xc = tid & 3;           // Xh: batch row, k-octet
    const int wnl = tid & 127, wrb = (tid >> 7) * 8; // Ws: n col, k-pair base

    float acc[2][4][4];
    #pragma unroll
    for (int i = 0; i < 2; i++)
        #pragma unroll
        for (int j = 0; j < 4; j++)
            #pragma unroll
            for (int c = 0; c < 4; c++) acc[i][j][c] = 0.0f;

    for (int k0 = 0; k0 < K; k0 += 32) {
        if (k0) __syncthreads();
        {   // Xh[b][k] fp16, k-contiguous (8 k per thread)
            const float* xp = X + (long long)xb * ldx + k0 + 8 * xc;
            float4 v0 = *(const float4*)xp;
            float4 v1 = *(const float4*)(xp + 4);
            uint4 pk;
            pk.x = pkh2(v0.x, v0.y);
            pk.y = pkh2(v0.z, v0.w);
            pk.z = pkh2(v1.x, v1.y);
            pk.w = pkh2(v1.z, v1.w);
            *(uint4*)&Xh[xb * KPW + 4 * xc] = pk;
        }
        {   // Ws[n][k] = W[k][n] transposed, 8 k-pairs per thread
            #pragma unroll
            for (int i = 0; i < 8; i++) {
                int r = wrb + i;                      // k-pair index 0..15
                const float* wp = W + (long long)(k0 + 2 * r) * ldw + wnl;
                float f0 = wp[0], f1 = wp[ldw];
                Ws[wnl * KPW + r] = pkh2(f0, f1);
            }
        }
        __syncthreads();

        #pragma unroll
        for (int kk = 0; kk < 2; kk++) {              // two k16 steps
            const int kw = kk * 8;                    // word offset (16 halves)
            uint32_t au[2][4];
            #pragma unroll
            for (int mt = 0; mt < 2; mt++) {
                const uint32_t* ap = &Xh[(bw + 16 * mt + gid) * KPW + kw + t4];
                au[mt][0] = ap[0];
                au[mt][1] = ap[8 * KPW];
                au[mt][2] = ap[4];
                au[mt][3] = ap[8 * KPW + 4];
            }
            uint32_t bu[4][2];
            #pragma unroll
            for (int nt = 0; nt < 4; nt++) {
                const uint32_t* bp = &Ws[(nw + 8 * nt + gid) * KPW + kw + t4];
                bu[nt][0] = bp[0];
                bu[nt][1] = bp[4];
            }
            #pragma unroll
            for (int mt = 0; mt < 2; mt++)
                #pragma unroll
                for (int nt = 0; nt < 4; nt++)
                    mma16816(acc[mt][nt][0], acc[mt][nt][1], acc[mt][nt][2], acc[mt][nt][3],
                             au[mt][0], au[mt][1], au[mt][2], au[mt][3],
                             bu[nt][0], bu[nt][1]);
        }
    }

    // epilogue: c0=(r,n) c1=(r,n+1) c2=(r+8,n) c3=(r+8,n+1)
    #pragma unroll
    for (int mt = 0; mt < 2; mt++) {
        const int r0 = bw + 16 * mt + gid;
        #pragma unroll
        for (int nt = 0; nt < 4; nt++) {
            const int n = nw + 8 * nt + 2 * t4;
            float v0 = acc[mt][nt][0] + bi[n];
            float v1 = acc[mt][nt][1] + bi[n + 1];
            float v2 = acc[mt][nt][2] + bi[n];
            float v3 = acc[mt][nt][3] + bi[n + 1];
            if (EPI >= 1) {
                v0 = fmaxf(v0, 0.0f); v1 = fmaxf(v1, 0.0f);
                v2 = fmaxf(v2, 0.0f); v3 = fmaxf(v3, 0.0f);
            }
            if (EPI == 2) { v0 = tanhf(v0); v1 = tanhf(v1); v2 = tanhf(v2); v3 = tanhf(v3); }
            *(float2*)&C[(long long)r0 * ldc + n]       = make_float2(v0, v1);
            *(float2*)&C[(long long)(r0 + 8) * ldc + n] = make_float2(v2, v3);
        }
    }
}

// mlp1: W1 & Wg1 fused.  grid(FF/128=8, 1, 64)
__global__ void __launch_bounds__(256) k_mlp1(const float* __restrict__ W1,
                                              const float* __restrict__ b1,
                                              const float* __restrict__ Wg1,
                                              const float* __restrict__ bg1)
{
    int z = blockIdx.z, zz = z & 31, m = zz & 7;
    int n0 = blockIdx.x * 128;
    const float* W = (z < 32 ? W1 : Wg1) + (long long)zz * TWOD_ * FF_ + n0;
    const float* bi = (z < 32 ? b1 : bg1) + (long long)zz * FF_ + n0;
    float* C = (z < 32 ? g_h : g_hg) + (long long)zz * B_ * FF_ + n0;
    hgemm<1>(g_x + (long long)m * B_ * TWOD_, TWOD_, W, FF_, C, FF_, bi, TWOD_);
}

// mlp2.  grid(D/128=4, 1, 32)
__global__ void __launch_bounds__(256) k_mlp2(const float* __restrict__ W2,
                                              const float* __restrict__ b2)
{
    int z = blockIdx.z, n0 = blockIdx.x * 128;
    hgemm<2>(g_h + (long long)z * B_ * FF_, FF_,
             W2 + (long long)z * FF_ * D_ + n0, D_,
             g_o + (long long)z * B_ * D_ + n0, D_,
             b2 + (long long)z * D_ + n0, FF_);
}

// ---------------- SIMT 64x64 GEMM core (attention odd shapes) ----------------
template<bool TB, int EPI>
__device__ __forceinline__ void gemm64(const float* __restrict__ A, int lda,
                                       const float* __restrict__ Bp, int ldb,
                                       float* __restrict__ C, int ldc,
                                       int K, const float* __restrict__ bias)
{
    __shared__ float As[16][64];
    __shared__ float Bs[16][64];
    const int tid = threadIdx.x;
    const int tx = tid & 15, ty = tid >> 4;
    const int ar = tid >> 2, ak = (tid & 3) << 2;
    const int nk = tid >> 4, nc = (tid & 15) << 2;
    float acc[4][4] = {};
    for (int k0 = 0; k0 < K; k0 += 16) {
        __syncthreads();
        float4 av = *(const float4*)(A + ar * lda + k0 + ak);
        As[ak + 0][ar] = av.x; As[ak + 1][ar] = av.y;
        As[ak + 2][ar] = av.z; As[ak + 3][ar] = av.w;
        if (TB) {
            float4 bv = *(const float4*)(Bp + ar * ldb + k0 + ak);
            Bs[ak + 0][ar] = bv.x; Bs[ak + 1][ar] = bv.y;
            Bs[ak + 2][ar] = bv.z; Bs[ak + 3][ar] = bv.w;
        } else {
            *(float4*)&Bs[nk][nc] = *(const float4*)(Bp + (k0 + nk) * ldb + nc);
        }
        __syncthreads();
        #pragma unroll
        for (int kk = 0; kk < 16; kk++) {
            float4 a4 = *(const float4*)&As[kk][ty << 2];
            float4 b4 = *(const float4*)&Bs[kk][tx << 2];
            float aa[4] = {a4.x, a4.y, a4.z, a4.w};
            float bb[4] = {b4.x, b4.y, b4.z, b4.w};
            #pragma unroll
            for (int i = 0; i < 4; i++)
                #pragma unroll
                for (int j = 0; j < 4; j++)
                    acc[i][j] += aa[i] * bb[j];
        }
    }
    #pragma unroll
    for (int i = 0; i < 4; i++) {
        int r = (ty << 2) + i;
        #pragma unroll
        for (int j = 0; j < 4; j++) {
            int c = (tx << 2) + j;
            float v = acc[i][j];
            if (bias) v += bias[c];
            if (EPI >= 1) v = fmaxf(v, 0.0f);
            C[r * ldc + c] = v;
        }
    }
}

__global__ void __launch_bounds__(256) k_qproj(const float* __restrict__ pq,
                                               const float* __restrict__ Wq,
                                               const float* __restrict__ bq)
{
    int m = blockIdx.z, n0 = blockIdx.x * 64;
    gemm64<false, 0>(pq + m * B_ * D_, D_,
                     Wq + m * D_ * D_ + n0, D_,
                     g_q + m * B_ * D_ + n0, D_, D_, bq + m * D_ + n0);
}

__global__ void __launch_bounds__(256) k_qk(const float* __restrict__ Wk)
{
    int m = blockIdx.z >> 3, h = blockIdx.z & 7, n0 = blockIdx.x * 64;
    gemm64<true, 0>(g_q + m * B_ * D_ + h * HD_, D_,
                    Wk + m * D_ * D_ + n0 * D_ + h * HD_, D_,
                    g_qk + (m * H_ + h) * D_ + n0, MH_ * D_, HD_, nullptr);
}

__global__ void __launch_bounds__(256) k_scores(const float* __restrict__ key_in)
{
    int b = blockIdx.z, n0 = blockIdx.x * 64;
    gemm64<true, 0>(g_qk + b * MH_ * D_, D_,
                    key_in + (long)n0 * B_ * D_ + b * D_, B_ * D_,
                    g_w + b * MH_ * S_ + n0, S_, D_, nullptr);
}

__global__ void __launch_bounds__(256) k_softmax(const float* __restrict__ bk)
{
    int row = blockIdx.x * 8 + (threadIdx.x >> 5);
    int lane = threadIdx.x & 31;
    int b = row >> 6, mh = row & 63;
    int m = mh >> 3, h = mh & 7;
    const float* qp  = g_q + m * B_ * D_ + b * D_ + h * HD_;
    const float* bkp = bk + m * D_ + h * HD_;
    float bias = qp[lane] * bkp[lane] + qp[lane + 32] * bkp[lane + 32];
    #pragma unroll
    for (int o = 16; o; o >>= 1) bias += __shfl_xor_sync(0xffffffffu, bias, o);
    float* wrow = g_w + b * MH_ * S_ + mh * S_;
    float v[4], mx = -INFINITY;
    #pragma unroll
    for (int i = 0; i < 4; i++) {
        v[i] = (wrow[lane + 32 * i] + bias) * 0.125f;
        mx = fmaxf(mx, v[i]);
    }
    #pragma unroll
    for (int o = 16; o; o >>= 1) mx = fmaxf(mx, __shfl_xor_sync(0xffffffffu, mx, o));
    float sum = 0.0f;
    #pragma unroll
    for (int i = 0; i < 4; i++) { v[i] = __expf(v[i] - mx); sum += v[i]; }
    #pragma unroll
    for (int o = 16; o; o >>= 1) sum += __shfl_xor_sync(0xffffffffu, sum, o);
    float inv = 1.0f / sum;
    #pragma unroll
    for (int i = 0; i < 4; i++) wrow[lane + 32 * i] = v[i] * inv;
}

__global__ void __launch_bounds__(256) k_wv(const float* __restrict__ value_in)
{
    int b = blockIdx.z, n0 = blockIdx.x * 64;
    gemm64<false, 0>(g_w + b * MH_ * S_, S_,
                     value_in + b * D_ + n0, B_ * D_,
                     g_wv + b * MH_ * D_ + n0, D_, S_, nullptr);
}

__global__ void __launch_bounds__(256) k_ao(const float* __restrict__ Wv,
                                            const float* __restrict__ bv)
{
    int m = blockIdx.z >> 3, h = blockIdx.z & 7;
    gemm64<false, 0>(g_wv + (m * H_ + h) * D_, MH_ * D_,
                     Wv + m * D_ * D_ + h * HD_, D_,
                     g_ao + m * B_ * D_ + h * HD_, D_, D_, bv + m * D_ + h * HD_);
}

__global__ void __launch_bounds__(256) k_attnout(const float* __restrict__ Wo,
                                                 const float* __restrict__ bo)
{
    int m = blockIdx.z, n0 = blockIdx.x * 64;
    gemm64<false, 1>(g_ao + m * B_ * D_, D_,
                     Wo + m * D_ * D_ + n0, D_,
                     g_x + m * B_ * TWOD_ + n0, TWOD_, D_, bo + m * D_ + n0);
}

__global__ void __launch_bounds__(256) k_xfill(const float* __restrict__ ps)
{
    int i = blockIdx.x * 256 + threadIdx.x;
    if (i < M_ * B_ * D_) {
        int mb = i >> 9, d = i & (D_ - 1);
        g_x[mb * TWOD_ + D_ + d] = fmaxf(ps[i], 0.0f);
    }
}

__global__ void __launch_bounds__(128) k_final(const float* __restrict__ Wg2,
                                               const float* __restrict__ bg2,
                                               const float* __restrict__ pq,
                                               const float* __restrict__ pk,
                                               const float* __restrict__ pv,
                                               const float* __restrict__ ps,
                                               float* __restrict__ out)
{
    int z = blockIdx.x;
    int g = z >> 9, rem = z & 511;
    int m = rem >> 6, b = rem & 63;
    int gm = g * M_ + m;
    int tid = threadIdx.x, lane = tid & 31;
    const float* hg = g_hg + ((long)gm * B_ + b) * FF_;
    const float* wg = Wg2 + (long)gm * FF_;
    float s = 0.0f;
    for (int f = tid; f < FF_; f += 128) s += hg[f] * wg[f];
    #pragma unroll
    for (int o = 16; o; o >>= 1) s += __shfl_xor_sync(0xffffffffu, s, o);
    __shared__ float red[4];
    if (lane == 0) red[tid >> 5] = s;
    __syncthreads();
    float tot = red[0] + red[1] + red[2] + red[3];
    float gate = 1.0f / (1.0f + __expf(-(tot + bg2[gm])));
    const float* prevs[4] = {pq, pk, pv, ps};
    const float* pr = prevs[g] + ((long)m * B_ + b) * D_;
    const float* ob = g_o + ((long)gm * B_ + b) * D_;
    float* dst = out + (((long)((g + 1) & 3) * M_ + m) * B_ + b) * D_;
    for (int d = tid; d < D_; d += 128)
        dst[d] = gate * ob[d] + (1.0f - gate) * pr[d];
}

// ---------------- launch ----------------
extern "C" void kernel_launch(void* const* d_in, const int* in_sizes, int n_in,
                              void* d_out, int out_size)
{
    const float* prev_state = (const float*)d_in[0];
    const float* prev_query = (const float*)d_in[1];
    const float* prev_key   = (const float*)d_in[2];
    const float* prev_value = (const float*)d_in[3];
    const float* key_in     = (const float*)d_in[4];
    const float* value_in   = (const float*)d_in[5];
    const float* Wq  = (const float*)d_in[6];
    const float* bq  = (const float*)d_in[7];
    const float* Wk  = (const float*)d_in[8];
    const float* bk  = (const float*)d_in[9];
    const float* Wv  = (const float*)d_in[10];
    const float* bv  = (const float*)d_in[11];
    const float* Wo  = (const float*)d_in[12];
    const float* bo  = (const float*)d_in[13];
    const float* W1  = (const float*)d_in[14];
    const float* b1  = (const float*)d_in[15];
    const float* W2  = (const float*)d_in[16];
    const float* b2  = (const float*)d_in[17];
    const float* Wg1 = (const float*)d_in[18];
    const float* bg1 = (const float*)d_in[19];
    const float* Wg2 = (const float*)d_in[20];
    const float* bg2 = (const float*)d_in[21];
    float* out = (float*)d_out;

    k_qproj  <<<dim3(D_ / 64, 1, M_),      256>>>(prev_query, Wq, bq);
    k_qk     <<<dim3(D_ / 64, 1, M_ * H_), 256>>>(Wk);
    k_scores <<<dim3(S_ / 64, 1, B_),      256>>>(key_in);
    k_softmax<<<(B_ * MH_) / 8,            256>>>(bk);
    k_wv     <<<dim3(D_ / 64, 1, B_),      256>>>(value_in);
    k_ao     <<<dim3(1, 1, M_ * H_),       256>>>(Wv, bv);
    k_attnout<<<dim3(D_ / 64, 1, M_),      256>>>(Wo, bo);
    k_xfill  <<<(M_ * B_ * D_ + 255) / 256, 256>>>(prev_state);
    k_mlp1   <<<dim3(FF_ / 128, 1, 64),    256>>>(W1, b1, Wg1, bg1);
    k_mlp2   <<<dim3(D_ / 128, 1, 32),     256>>>(W2, b2);
    k_final  <<<4 * M_ * B_, 128>>>(Wg2, bg2, prev_query, prev_key,
                                    prev_value, prev_state, out);
}

// round 16
// speedup vs baseline: 2.5443x; 1.1225x over previous
#include <cuda_runtime.h>
#include <cuda_fp16.h>
#include <math.h>
#include <stdint.h>

#define M_    8
#define B_    64
#define S_    128
#define D_    512
#define H_    8
#define HD_   64
#define FF_   1024
#define MH_   64
#define TWOD_ 1024

// ---------------- scratch ----------------
__device__ float g_q [M_*B_*D_];
__device__ float g_qk[B_*MH_*D_];
__device__ float g_w [B_*MH_*S_];
__device__ float g_wv[B_*MH_*D_];
__device__ float g_ao[M_*B_*D_];
__device__ float g_x [M_*B_*TWOD_];
__device__ float g_h [4*M_*B_*FF_];
__device__ float g_hg[4*M_*B_*FF_];
__device__ float g_o [4*M_*B_*D_];

__device__ __forceinline__ uint32_t pkh2(float a, float b) {
    __half2 h = __floats2half2_rn(a, b);
    return *reinterpret_cast<uint32_t*>(&h);
}

// ================= fp16 mma.sync GEMM =================
// C[r][n] = epi(sum_k X[r][k] * W[k][n] + bias[n]);  f32 in/out, fp16 mma, f32 acc.
// CTA tile: 64 rows (mma M) x 128 cols (mma N); 8 warps = 2(r) x 4(n), warp 32x32.
// Smem rows KPW=20 words (80 B): 16B-aligned AND conflict-free fragment loads.
// WMODE 0: W k-major [k][n] strided rows (weights).  WMODE 1: W n-major [n][k],
// k contiguous (key rows / Wk rows) -> coalesced vector loader.
#define KPW 20

__device__ __forceinline__ void mma16816(float& c0, float& c1, float& c2, float& c3,
                                         uint32_t a0, uint32_t a1, uint32_t a2, uint32_t a3,
                                         uint32_t b0, uint32_t b1) {
    asm volatile("mma.sync.aligned.m16n8k16.row.col.f32.f16.f16.f32 "
                 "{%0,%1,%2,%3}, {%4,%5,%6,%7}, {%8,%9}, {%0,%1,%2,%3};"
                 : "+f"(c0), "+f"(c1), "+f"(c2), "+f"(c3)
                 : "r"(a0), "r"(a1), "r"(a2), "r"(a3), "r"(b0), "r"(b1));
}

template<int WMODE, int EPI>
__device__ __forceinline__ void hgemm(const float* __restrict__ X, int ldx,
                                      const float* __restrict__ W, long long ldw,
                                      float* __restrict__ C, int ldc,
                                      const float* __restrict__ bi, int K)
{
    __shared__ __align__(16) uint32_t Xh[64 * KPW];    // [r][kw]
    __shared__ __align__(16) uint32_t Ws[128 * KPW];   // [n][kw]

    const int tid = threadIdx.x, lane = tid & 31, warp = tid >> 5;
    const int wb = warp >> 2, wn = warp & 3;
    const int bw = wb * 32, nw = wn * 32;
    const int gid = lane >> 2, t4 = lane & 3;

    const int xb = tid >> 2, xc = tid & 3;           // Xh loader: row, k-octet
    const int wnl = tid & 127, wrb = (tid >> 7) * 8; // WMODE0: n col, k-pair base
    const int r2 = tid >> 1, hf = tid & 1;           // WMODE1: n row, k-half

    float acc[2][4][4];
    #pragma unroll
    for (int i = 0; i < 2; i++)
        #pragma unroll
        for (int j = 0; j < 4; j++)
            #pragma unroll
            for (int c = 0; c < 4; c++) acc[i][j][c] = 0.0f;

    for (int k0 = 0; k0 < K; k0 += 32) {
        if (k0) __syncthreads();
        {   // Xh[r][k] fp16, k-contiguous (8 k per thread)
            const float* xp = X + (long long)xb * ldx + k0 + 8 * xc;
            float4 v0 = *(const float4*)xp;
            float4 v1 = *(const float4*)(xp + 4);
            uint4 pk;
            pk.x = pkh2(v0.x, v0.y);
            pk.y = pkh2(v0.z, v0.w);
            pk.z = pkh2(v1.x, v1.y);
            pk.w = pkh2(v1.z, v1.w);
            *(uint4*)&Xh[xb * KPW + 4 * xc] = pk;
        }
        if (WMODE == 0) {   // Ws[n][k] = W[k][n] transposed, 8 k-pairs per thread
            #pragma unroll
            for (int i = 0; i < 8; i++) {
                int r = wrb + i;                      // k-pair index 0..15
                const float* wp = W + (long long)(k0 + 2 * r) * ldw + wnl;
                float f0 = wp[0], f1 = wp[ldw];
                Ws[wnl * KPW + r] = pkh2(f0, f1);
            }
        } else {            // Ws[n][k] = W[n][k] direct, vectorized (16 k per thread)
            const float* wp = W + (long long)r2 * ldw + k0 + 16 * hf;
            float4 a = *(const float4*)wp;
            float4 b = *(const float4*)(wp + 4);
            float4 c = *(const float4*)(wp + 8);
            float4 d = *(const float4*)(wp + 12);
            uint4 p0, p1;
            p0.x = pkh2(a.x, a.y); p0.y = pkh2(a.z, a.w);
            p0.z = pkh2(b.x, b.y); p0.w = pkh2(b.z, b.w);
            p1.x = pkh2(c.x, c.y); p1.y = pkh2(c.z, c.w);
            p1.z = pkh2(d.x, d.y); p1.w = pkh2(d.z, d.w);
            *(uint4*)&Ws[r2 * KPW + 8 * hf]     = p0;
            *(uint4*)&Ws[r2 * KPW + 8 * hf + 4] = p1;
        }
        __syncthreads();

        #pragma unroll
        for (int kk = 0; kk < 2; kk++) {              // two k16 steps
            const int kw = kk * 8;
            uint32_t au[2][4];
            #pragma unroll
            for (int mt = 0; mt < 2; mt++) {
                const uint32_t* ap = &Xh[(bw + 16 * mt + gid) * KPW + kw + t4];
                au[mt][0] = ap[0];
                au[mt][1] = ap[8 * KPW];
                au[mt][2] = ap[4];
                au[mt][3] = ap[8 * KPW + 4];
            }
            uint32_t bu[4][2];
            #pragma unroll
            for (int nt = 0; nt < 4; nt++) {
                const uint32_t* bp = &Ws[(nw + 8 * nt + gid) * KPW + kw + t4];
                bu[nt][0] = bp[0];
                bu[nt][1] = bp[4];
            }
            #pragma unroll
            for (int mt = 0; mt < 2; mt++)
                #pragma unroll
                for (int nt = 0; nt < 4; nt++)
                    mma16816(acc[mt][nt][0], acc[mt][nt][1], acc[mt][nt][2], acc[mt][nt][3],
                             au[mt][0], au[mt][1], au[mt][2], au[mt][3],
                             bu[nt][0], bu[nt][1]);
        }
    }

    // epilogue: c0=(r,n) c1=(r,n+1) c2=(r+8,n) c3=(r+8,n+1)
    #pragma unroll
    for (int mt = 0; mt < 2; mt++) {
        const int r0 = bw + 16 * mt + gid;
        #pragma unroll
        for (int nt = 0; nt < 4; nt++) {
            const int n = nw + 8 * nt + 2 * t4;
            float b0 = bi ? bi[n] : 0.0f;
            float b1 = bi ? bi[n + 1] : 0.0f;
            float v0 = acc[mt][nt][0] + b0;
            float v1 = acc[mt][nt][1] + b1;
            float v2 = acc[mt][nt][2] + b0;
            float v3 = acc[mt][nt][3] + b1;
            if (EPI >= 1) {
                v0 = fmaxf(v0, 0.0f); v1 = fmaxf(v1, 0.0f);
                v2 = fmaxf(v2, 0.0f); v3 = fmaxf(v3, 0.0f);
            }
            if (EPI == 2) { v0 = tanhf(v0); v1 = tanhf(v1); v2 = tanhf(v2); v3 = tanhf(v3); }
            *(float2*)&C[(long long)r0 * ldc + n]       = make_float2(v0, v1);
            *(float2*)&C[(long long)(r0 + 8) * ldc + n] = make_float2(v2, v3);
        }
    }
}

// ---------------- hgemm stage wrappers ----------------

// q = prev_query @ Wq + bq.  grid(4, 1, 8)
__global__ void __launch_bounds__(256) h_qproj(const float* __restrict__ pq,
                                               const float* __restrict__ Wq,
                                               const float* __restrict__ bq)
{
    int m = blockIdx.z, n0 = blockIdx.x * 128;
    hgemm<0, 0>(pq + m * B_ * D_, D_,
                Wq + (long long)m * D_ * D_ + n0, D_,
                g_q + m * B_ * D_ + n0, D_, bq + m * D_ + n0, D_);
}

// qk[b][mh][c] = sum_d q[m,b,h64+d] * Wk[m,c,h64+d].  grid(4, 1, 64), z=(m,h)
__global__ void __launch_bounds__(256) h_qk(const float* __restrict__ Wk)
{
    int m = blockIdx.z >> 3, h = blockIdx.z & 7, n0 = blockIdx.x * 128;
    hgemm<1, 0>(g_q + m * B_ * D_ + h * HD_, D_,
                Wk + (long long)m * D_ * D_ + (long long)n0 * D_ + h * HD_, D_,
                g_qk + (m * H_ + h) * D_ + n0, MH_ * D_, nullptr, HD_);
}

// scores[b][mh][s] = sum_c qk[b,mh,c] * key_in[s,b,c].  grid(1, 1, 64), z=b
__global__ void __launch_bounds__(256) h_scores(const float* __restrict__ key_in)
{
    int b = blockIdx.z;
    hgemm<1, 0>(g_qk + b * MH_ * D_, D_,
                key_in + (long long)b * D_, (long long)B_ * D_,
                g_w + b * MH_ * S_, S_, nullptr, D_);
}

// wv[b][mh][c] = sum_s w[b,mh,s] * value_in[s,b,c].  grid(4, 1, 64), z=b
__global__ void __launch_bounds__(256) h_wv(const float* __restrict__ value_in)
{
    int b = blockIdx.z, n0 = blockIdx.x * 128;
    hgemm<0, 0>(g_w + b * MH_ * S_, S_,
                value_in + (long long)b * D_ + n0, (long long)B_ * D_,
                g_wv + b * MH_ * D_ + n0, D_, nullptr, S_);
}

// x[:,0:D] = relu(ao @ Wo + bo).  grid(4, 1, 8)
__global__ void __launch_bounds__(256) h_attnout(const float* __restrict__ Wo,
                                                 const float* __restrict__ bo)
{
    int m = blockIdx.z, n0 = blockIdx.x * 128;
    hgemm<0, 1>(g_ao + m * B_ * D_, D_,
                Wo + (long long)m * D_ * D_ + n0, D_,
                g_x + m * B_ * TWOD_ + n0, TWOD_, bo + m * D_ + n0, D_);
}

// mlp1: W1 & Wg1 fused.  grid(8, 1, 64)
__global__ void __launch_bounds__(256) k_mlp1(const float* __restrict__ W1,
                                              const float* __restrict__ b1,
                                              const float* __restrict__ Wg1,
                                              const float* __restrict__ bg1)
{
    int z = blockIdx.z, zz = z & 31, m = zz & 7;
    int n0 = blockIdx.x * 128;
    const float* W = (z < 32 ? W1 : Wg1) + (long long)zz * TWOD_ * FF_ + n0;
    const float* bi = (z < 32 ? b1 : bg1) + (long long)zz * FF_ + n0;
    float* C = (z < 32 ? g_h : g_hg) + (long long)zz * B_ * FF_ + n0;
    hgemm<0, 1>(g_x + (long long)m * B_ * TWOD_, TWOD_, W, FF_, C, FF_, bi, TWOD_);
}

// mlp2.  grid(4, 1, 32)
__global__ void __launch_bounds__(256) k_mlp2(const float* __restrict__ W2,
                                              const float* __restrict__ b2)
{
    int z = blockIdx.z, n0 = blockIdx.x * 128;
    hgemm<0, 2>(g_h + (long long)z * B_ * FF_, FF_,
                W2 + (long long)z * FF_ * D_ + n0, D_,
                g_o + (long long)z * B_ * D_ + n0, D_,
                b2 + (long long)z * D_ + n0, FF_);
}

// ---------------- SIMT 64x64 GEMM core (k_ao only) ----------------
template<bool TB, int EPI>
__device__ __forceinline__ void gemm64(const float* __restrict__ A, int lda,
                                       const float* __restrict__ Bp, int ldb,
                                       float* __restrict__ C, int ldc,
                                       int K, const float* __restrict__ bias)
{
    __shared__ float As[16][64];
    __shared__ float Bs[16][64];
    const int tid = threadIdx.x;
    const int tx = tid & 15, ty = tid >> 4;
    const int ar = tid >> 2, ak = (tid & 3) << 2;
    const int nk = tid >> 4, nc = (tid & 15) << 2;
    float acc[4][4] = {};
    for (int k0 = 0; k0 < K; k0 += 16) {
        __syncthreads();
        float4 av = *(const float4*)(A + ar * lda + k0 + ak);
        As[ak + 0][ar] = av.x; As[ak + 1][ar] = av.y;
        As[ak + 2][ar] = av.z; As[ak + 3][ar] = av.w;
        if (TB) {
            float4 bv = *(const float4*)(Bp + ar * ldb + k0 + ak);
            Bs[ak + 0][ar] = bv.x; Bs[ak + 1][ar] = bv.y;
            Bs[ak + 2][ar] = bv.z; Bs[ak + 3][ar] = bv.w;
        } else {
            *(float4*)&Bs[nk][nc] = *(const float4*)(Bp + (k0 + nk) * ldb + nc);
        }
        __syncthreads();
        #pragma unroll
        for (int kk = 0; kk < 16; kk++) {
            float4 a4 = *(const float4*)&As[kk][ty << 2];
            float4 b4 = *(const float4*)&Bs[kk][tx << 2];
            float aa[4] = {a4.x, a4.y, a4.z, a4.w};
            float bb[4] = {b4.x, b4.y, b4.z, b4.w};
            #pragma unroll
            for (int i = 0; i < 4; i++)
                #pragma unroll
                for (int j = 0; j < 4; j++)
                    acc[i][j] += aa[i] * bb[j];
        }
    }
    #pragma unroll
    for (int i = 0; i < 4; i++) {
        int r = (ty << 2) + i;
        #pragma unroll
        for (int j = 0; j < 4; j++) {
            int c = (tx << 2) + j;
            float v = acc[i][j];
            if (bias) v += bias[c];
            if (EPI >= 1) v = fmaxf(v, 0.0f);
            C[r * ldc + c] = v;
        }
    }
}

__global__ void __launch_bounds__(256) k_ao(const float* __restrict__ Wv,
                                            const float* __restrict__ bv)
{
    int m = blockIdx.z >> 3, h = blockIdx.z & 7;
    gemm64<false, 0>(g_wv + (m * H_ + h) * D_, MH_ * D_,
                     Wv + m * D_ * D_ + h * HD_, D_,
                     g_ao + m * B_ * D_ + h * HD_, D_, D_, bv + m * D_ + h * HD_);
}

__global__ void __launch_bounds__(256) k_softmax(const float* __restrict__ bk)
{
    int row = blockIdx.x * 8 + (threadIdx.x >> 5);
    int lane = threadIdx.x & 31;
    int b = row >> 6, mh = row & 63;
    int m = mh >> 3, h = mh & 7;
    const float* qp  = g_q + m * B_ * D_ + b * D_ + h * HD_;
    const float* bkp = bk + m * D_ + h * HD_;
    float bias = qp[lane] * bkp[lane] + qp[lane + 32] * bkp[lane + 32];
    #pragma unroll
    for (int o = 16; o; o >>= 1) bias += __shfl_xor_sync(0xffffffffu, bias, o);
    float* wrow = g_w + b * MH_ * S_ + mh * S_;
    float v[4], mx = -INFINITY;
    #pragma unroll
    for (int i = 0; i < 4; i++) {
        v[i] = (wrow[lane + 32 * i] + bias) * 0.125f;
        mx = fmaxf(mx, v[i]);
    }
    #pragma unroll
    for (int o = 16; o; o >>= 1) mx = fmaxf(mx, __shfl_xor_sync(0xffffffffu, mx, o));
    float sum = 0.0f;
    #pragma unroll
    for (int i = 0; i < 4; i++) { v[i] = __expf(v[i] - mx); sum += v[i]; }
    #pragma unroll
    for (int o = 16; o; o >>= 1) sum += __shfl_xor_sync(0xffffffffu, sum, o);
    float inv = 1.0f / sum;
    #pragma unroll
    for (int i = 0; i < 4; i++) wrow[lane + 32 * i] = v[i] * inv;
}

__global__ void __launch_bounds__(256) k_xfill(const float* __restrict__ ps)
{
    int i = blockIdx.x * 256 + threadIdx.x;
    if (i < M_ * B_ * D_) {
        int mb = i >> 9, d = i & (D_ - 1);
        g_x[mb * TWOD_ + D_ + d] = fmaxf(ps[i], 0.0f);
    }
}

__global__ void __launch_bounds__(128) k_final(const float* __restrict__ Wg2,
                                               const float* __restrict__ bg2,
                                               const float* __restrict__ pq,
                                               const float* __restrict__ pk,
                                               const float* __restrict__ pv,
                                               const float* __restrict__ ps,
                                               float* __restrict__ out)
{
    int z = blockIdx.x;
    int g = z >> 9, rem = z & 511;
    int m = rem >> 6, b = rem & 63;
    int gm = g * M_ + m;
    int tid = threadIdx.x, lane = tid & 31;
    const float* hg = g_hg + ((long)gm * B_ + b) * FF_;
    const float* wg = Wg2 + (long)gm * FF_;
    float s = 0.0f;
    for (int f = tid; f < FF_; f += 128) s += hg[f] * wg[f];
    #pragma unroll
    for (int o = 16; o; o >>= 1) s += __shfl_xor_sync(0xffffffffu, s, o);
    __shared__ float red[4];
    if (lane == 0) red[tid >> 5] = s;
    __syncthreads();
    float tot = red[0] + red[1] + red[2] + red[3];
    float gate = 1.0f / (1.0f + __expf(-(tot + bg2[gm])));
    const float* prevs[4] = {pq, pk, pv, ps};
    const float* pr = prevs[g] + ((long)m * B_ + b) * D_;
    const float* ob = g_o + ((long)gm * B_ + b) * D_;
    float* dst = out + (((long)((g + 1) & 3) * M_ + m) * B_ + b) * D_;
    for (int d = tid; d < D_; d += 128)
        dst[d] = gate * ob[d] + (1.0f - gate) * pr[d];
}

// ---------------- launch ----------------
extern "C" void kernel_launch(void* const* d_in, const int* in_sizes, int n_in,
                              void* d_out, int out_size)
{
    const float* prev_state = (const float*)d_in[0];
    const float* prev_query = (const float*)d_in[1];
    const float* prev_key   = (const float*)d_in[2];
    const float* prev_value = (const float*)d_in[3];
    const float* key_in     = (const float*)d_in[4];
    const float* value_in   = (const float*)d_in[5];
    const float* Wq  = (const float*)d_in[6];
    const float* bq  = (const float*)d_in[7];
    const float* Wk  = (const float*)d_in[8];
    const float* bk  = (const float*)d_in[9];
    const float* Wv  = (const float*)d_in[10];
    const float* bv  = (const float*)d_in[11];
    const float* Wo  = (const float*)d_in[12];
    const float* bo  = (const float*)d_in[13];
    const float* W1  = (const float*)d_in[14];
    const float* b1  = (const float*)d_in[15];
    const float* W2  = (const float*)d_in[16];
    const float* b2  = (const float*)d_in[17];
    const float* Wg1 = (const float*)d_in[18];
    const float* bg1 = (const float*)d_in[19];
    const float* Wg2 = (const float*)d_in[20];
    const float* bg2 = (const float*)d_in[21];
    float* out = (float*)d_out;

    h_qproj  <<<dim3(4, 1, M_),            256>>>(prev_query, Wq, bq);
    h_qk     <<<dim3(4, 1, M_ * H_),       256>>>(Wk);
    h_scores <<<dim3(1, 1, B_),            256>>>(key_in);
    k_softmax<<<(B_ * MH_) / 8,            256>>>(bk);
    h_wv     <<<dim3(4, 1, B_),            256>>>(value_in);
    k_ao     <<<dim3(1, 1, M_ * H_),       256>>>(Wv, bv);
    h_attnout<<<dim3(4, 1, M_),            256>>>(Wo, bo);
    k_xfill  <<<(M_ * B_ * D_ + 255) / 256, 256>>>(prev_state);
    k_mlp1   <<<dim3(FF_ / 128, 1, 64),    256>>>(W1, b1, Wg1, bg1);
    k_mlp2   <<<dim3(D_ / 128, 1, 32),     256>>>(W2, b2);
    k_final  <<<4 * M_ * B_, 128>>>(Wg2, bg2, prev_query, prev_key,
                                    prev_value, prev_state, out);
}

// round 17
// speedup vs baseline: 3.3775x; 1.3275x over previous
#include <cuda_runtime.h>
#include <cuda_fp16.h>
#include <math.h>
#include <stdint.h>

#define M_    8
#define B_    64
#define S_    128
#define D_    512
#define H_    8
#define HD_   64
#define FF_   1024
#define MH_   64
#define TWOD_ 1024

// ---------------- scratch ----------------
__device__ float g_q [M_*B_*D_];
__device__ float g_qk[B_*MH_*D_];
__device__ float g_w [B_*MH_*S_];
__device__ float g_wv[B_*MH_*D_];
__device__ float g_ao[M_*B_*D_];
__device__ float g_x [M_*B_*TWOD_];
__device__ float g_h [4*M_*B_*FF_];
__device__ float g_hg[4*M_*B_*FF_];
__device__ float g_o [4*M_*B_*D_];

__device__ __forceinline__ uint32_t pkh2(float a, float b) {
    __half2 h = __floats2half2_rn(a, b);
    return *reinterpret_cast<uint32_t*>(&h);
}

// ================= fp16 mma.sync GEMM, register double-buffered =================
// C[r][n] = epi(sum_k X[r][k] * W[k][n] + bias[n]);  f32 in/out, fp16 mma, f32 acc.
// CTA tile: 64 rows (mma M) x 128 cols (mma N); 8 warps = 2(r) x 4(n), warp 32x32.
// Smem rows KPW=20 words (80 B): 16B-aligned AND conflict-free fragment loads.
// WMODE 0: W k-major [k][n] strided rows.  WMODE 1: W n-major [n][k], k contiguous.
// Pipeline: store chunk c to smem -> sync -> prefetch chunk c+1 LDGs (latency
// overlapped) -> MMA on chunk c -> sync.
#define KPW 20

__device__ __forceinline__ void mma16816(float& c0, float& c1, float& c2, float& c3,
                                         uint32_t a0, uint32_t a1, uint32_t a2, uint32_t a3,
                                         uint32_t b0, uint32_t b1) {
    asm volatile("mma.sync.aligned.m16n8k16.row.col.f32.f16.f16.f32 "
                 "{%0,%1,%2,%3}, {%4,%5,%6,%7}, {%8,%9}, {%0,%1,%2,%3};"
                 : "+f"(c0), "+f"(c1), "+f"(c2), "+f"(c3)
                 : "r"(a0), "r"(a1), "r"(a2), "r"(a3), "r"(b0), "r"(b1));
}

template<int WMODE, int EPI>
__device__ __forceinline__ void hgemm(const float* __restrict__ X, int ldx,
                                      const float* __restrict__ W, long long ldw,
                                      float* __restrict__ C, int ldc,
                                      const float* __restrict__ bi, int K)
{
    __shared__ __align__(16) uint32_t Xh[64 * KPW];    // [r][kw]
    __shared__ __align__(16) uint32_t Ws[128 * KPW];   // [n][kw]

    const int tid = threadIdx.x, lane = tid & 31, warp = tid >> 5;
    const int wb = warp >> 2, wn = warp & 3;
    const int bw = wb * 32, nw = wn * 32;
    const int gid = lane >> 2, t4 = lane & 3;

    const int xb = tid >> 2, xc = tid & 3;           // Xh loader: row, k-octet
    const int wnl = tid & 127, wrb = (tid >> 7) * 8; // WMODE0: n col, k-pair base
    const int r2 = tid >> 1, hf = tid & 1;           // WMODE1: n row, k-half

    float acc[2][4][4];
    #pragma unroll
    for (int i = 0; i < 2; i++)
        #pragma unroll
        for (int j = 0; j < 4; j++)
            #pragma unroll
            for (int c = 0; c < 4; c++) acc[i][j][c] = 0.0f;

    const int nchunk = K >> 5;

    float xr[8];            // X prefetch regs
    float wr[16];           // W prefetch regs

    // ---- prefetch chunk 0 ----
    {
        const float* xp = X + (long long)xb * ldx + 8 * xc;
        *(float4*)&xr[0] = *(const float4*)xp;
        *(float4*)&xr[4] = *(const float4*)(xp + 4);
        if (WMODE == 0) {
            #pragma unroll
            for (int i = 0; i < 8; i++) {
                const float* wp = W + (long long)(2 * (wrb + i)) * ldw + wnl;
                wr[2 * i]     = wp[0];
                wr[2 * i + 1] = wp[ldw];
            }
        } else {
            const float* wp = W + (long long)r2 * ldw + 16 * hf;
            *(float4*)&wr[0]  = *(const float4*)wp;
            *(float4*)&wr[4]  = *(const float4*)(wp + 4);
            *(float4*)&wr[8]  = *(const float4*)(wp + 8);
            *(float4*)&wr[12] = *(const float4*)(wp + 12);
        }
    }

    for (int c = 0; c < nchunk; c++) {
        // ---- store prefetched chunk c to smem ----
        {
            uint4 pk;
            pk.x = pkh2(xr[0], xr[1]);
            pk.y = pkh2(xr[2], xr[3]);
            pk.z = pkh2(xr[4], xr[5]);
            pk.w = pkh2(xr[6], xr[7]);
            *(uint4*)&Xh[xb * KPW + 4 * xc] = pk;
        }
        if (WMODE == 0) {
            #pragma unroll
            for (int i = 0; i < 8; i++)
                Ws[wnl * KPW + wrb + i] = pkh2(wr[2 * i], wr[2 * i + 1]);
        } else {
            uint4 p0, p1;
            p0.x = pkh2(wr[0], wr[1]);   p0.y = pkh2(wr[2], wr[3]);
            p0.z = pkh2(wr[4], wr[5]);   p0.w = pkh2(wr[6], wr[7]);
            p1.x = pkh2(wr[8], wr[9]);   p1.y = pkh2(wr[10], wr[11]);
            p1.z = pkh2(wr[12], wr[13]); p1.w = pkh2(wr[14], wr[15]);
            *(uint4*)&Ws[r2 * KPW + 8 * hf]     = p0;
            *(uint4*)&Ws[r2 * KPW + 8 * hf + 4] = p1;
        }
        __syncthreads();

        // ---- prefetch chunk c+1 (LDG latency overlaps the MMA section) ----
        if (c + 1 < nchunk) {
            const int k1 = (c + 1) << 5;
            const float* xp = X + (long long)xb * ldx + k1 + 8 * xc;
            *(float4*)&xr[0] = *(const float4*)xp;
            *(float4*)&xr[4] = *(const float4*)(xp + 4);
            if (WMODE == 0) {
                #pragma unroll
                for (int i = 0; i < 8; i++) {
                    const float* wp = W + (long long)(k1 + 2 * (wrb + i)) * ldw + wnl;
                    wr[2 * i]     = wp[0];
                    wr[2 * i + 1] = wp[ldw];
                }
            } else {
                const float* wp = W + (long long)r2 * ldw + k1 + 16 * hf;
                *(float4*)&wr[0]  = *(const float4*)wp;
                *(float4*)&wr[4]  = *(const float4*)(wp + 4);
                *(float4*)&wr[8]  = *(const float4*)(wp + 8);
                *(float4*)&wr[12] = *(const float4*)(wp + 12);
            }
        }

        // ---- MMA on chunk c ----
        #pragma unroll
        for (int kk = 0; kk < 2; kk++) {              // two k16 steps
            const int kw = kk * 8;
            uint32_t au[2][4];
            #pragma unroll
            for (int mt = 0; mt < 2; mt++) {
                const uint32_t* ap = &Xh[(bw + 16 * mt + gid) * KPW + kw + t4];
                au[mt][0] = ap[0];
                au[mt][1] = ap[8 * KPW];
                au[mt][2] = ap[4];
                au[mt][3] = ap[8 * KPW + 4];
            }
            uint32_t bu[4][2];
            #pragma unroll
            for (int nt = 0; nt < 4; nt++) {
                const uint32_t* bp = &Ws[(nw + 8 * nt + gid) * KPW + kw + t4];
                bu[nt][0] = bp[0];
                bu[nt][1] = bp[4];
            }
            #pragma unroll
            for (int mt = 0; mt < 2; mt++)
                #pragma unroll
                for (int nt = 0; nt < 4; nt++)
                    mma16816(acc[mt][nt][0], acc[mt][nt][1], acc[mt][nt][2], acc[mt][nt][3],
                             au[mt][0], au[mt][1], au[mt][2], au[mt][3],
                             bu[nt][0], bu[nt][1]);
        }
        if (c + 1 < nchunk) __syncthreads();
    }

    // epilogue: c0=(r,n) c1=(r,n+1) c2=(r+8,n) c3=(r+8,n+1)
    #pragma unroll
    for (int mt = 0; mt < 2; mt++) {
        const int r0 = bw + 16 * mt + gid;
        #pragma unroll
        for (int nt = 0; nt < 4; nt++) {
            const int n = nw + 8 * nt + 2 * t4;
            float b0 = bi ? bi[n] : 0.0f;
            float b1 = bi ? bi[n + 1] : 0.0f;
            float v0 = acc[mt][nt][0] + b0;
            float v1 = acc[mt][nt][1] + b1;
            float v2 = acc[mt][nt][2] + b0;
            float v3 = acc[mt][nt][3] + b1;
            if (EPI >= 1) {
                v0 = fmaxf(v0, 0.0f); v1 = fmaxf(v1, 0.0f);
                v2 = fmaxf(v2, 0.0f); v3 = fmaxf(v3, 0.0f);
            }
            if (EPI == 2) { v0 = tanhf(v0); v1 = tanhf(v1); v2 = tanhf(v2); v3 = tanhf(v3); }
            *(float2*)&C[(long long)r0 * ldc + n]       = make_float2(v0, v1);
            *(float2*)&C[(long long)(r0 + 8) * ldc + n] = make_float2(v2, v3);
        }
    }
}

// ---------------- hgemm stage wrappers ----------------

__global__ void __launch_bounds__(256) h_qproj(const float* __restrict__ pq,
                                               const float* __restrict__ Wq,
                                               const float* __restrict__ bq)
{
    int m = blockIdx.z, n0 = blockIdx.x * 128;
    hgemm<0, 0>(pq + m * B_ * D_, D_,
                Wq + (long long)m * D_ * D_ + n0, D_,
                g_q + m * B_ * D_ + n0, D_, bq + m * D_ + n0, D_);
}

__global__ void __launch_bounds__(256) h_qk(const float* __restrict__ Wk)
{
    int m = blockIdx.z >> 3, h = blockIdx.z & 7, n0 = blockIdx.x * 128;
    hgemm<1, 0>(g_q + m * B_ * D_ + h * HD_, D_,
                Wk + (long long)m * D_ * D_ + (long long)n0 * D_ + h * HD_, D_,
                g_qk + (m * H_ + h) * D_ + n0, MH_ * D_, nullptr, HD_);
}

__global__ void __launch_bounds__(256) h_scores(const float* __restrict__ key_in)
{
    int b = blockIdx.z;
    hgemm<1, 0>(g_qk + b * MH_ * D_, D_,
                key_in + (long long)b * D_, (long long)B_ * D_,
                g_w + b * MH_ * S_, S_, nullptr, D_);
}

__global__ void __launch_bounds__(256) h_wv(const float* __restrict__ value_in)
{
    int b = blockIdx.z, n0 = blockIdx.x * 128;
    hgemm<0, 0>(g_w + b * MH_ * S_, S_,
                value_in + (long long)b * D_ + n0, (long long)B_ * D_,
                g_wv + b * MH_ * D_ + n0, D_, nullptr, S_);
}

__global__ void __launch_bounds__(256) h_attnout(const float* __restrict__ Wo,
                                                 const float* __restrict__ bo)
{
    int m = blockIdx.z, n0 = blockIdx.x * 128;
    hgemm<0, 1>(g_ao + m * B_ * D_, D_,
                Wo + (long long)m * D_ * D_ + n0, D_,
                g_x + m * B_ * TWOD_ + n0, TWOD_, bo + m * D_ + n0, D_);
}

__global__ void __launch_bounds__(256) k_mlp1(const float* __restrict__ W1,
                                              const float* __restrict__ b1,
                                              const float* __restrict__ Wg1,
                                              const float* __restrict__ bg1)
{
    int z = blockIdx.z, zz = z & 31, m = zz & 7;
    int n0 = blockIdx.x * 128;
    const float* W = (z < 32 ? W1 : Wg1) + (long long)zz * TWOD_ * FF_ + n0;
    const float* bi = (z < 32 ? b1 : bg1) + (long long)zz * FF_ + n0;
    float* C = (z < 32 ? g_h : g_hg) + (long long)zz * B_ * FF_ + n0;
    hgemm<0, 1>(g_x + (long long)m * B_ * TWOD_, TWOD_, W, FF_, C, FF_, bi, TWOD_);
}

__global__ void __launch_bounds__(256) k_mlp2(const float* __restrict__ W2,
                                              const float* __restrict__ b2)
{
    int z = blockIdx.z, n0 = blockIdx.x * 128;
    hgemm<0, 2>(g_h + (long long)z * B_ * FF_, FF_,
                W2 + (long long)z * FF_ * D_ + n0, D_,
                g_o + (long long)z * B_ * D_ + n0, D_,
                b2 + (long long)z * D_ + n0, FF_);
}

// ---------------- SIMT 64x64 GEMM core (k_ao only) ----------------
template<bool TB, int EPI>
__device__ __forceinline__ void gemm64(const float* __restrict__ A, int lda,
                                       const float* __restrict__ Bp, int ldb,
                                       float* __restrict__ C, int ldc,
                                       int K, const float* __restrict__ bias)
{
    __shared__ float As[16][64];
    __shared__ float Bs[16][64];
    const int tid = threadIdx.x;
    const int tx = tid & 15, ty = tid >> 4;
    const int ar = tid >> 2, ak = (tid & 3) << 2;
    const int nk = tid >> 4, nc = (tid & 15) << 2;
    float acc[4][4] = {};
    for (int k0 = 0; k0 < K; k0 += 16) {
        __syncthreads();
        float4 av = *(const float4*)(A + ar * lda + k0 + ak);
        As[ak + 0][ar] = av.x; As[ak + 1][ar] = av.y;
        As[ak + 2][ar] = av.z; As[ak + 3][ar] = av.w;
        if (TB) {
            float4 bv = *(const float4*)(Bp + ar * ldb + k0 + ak);
            Bs[ak + 0][ar] = bv.x; Bs[ak + 1][ar] = bv.y;
            Bs[ak + 2][ar] = bv.z; Bs[ak + 3][ar] = bv.w;
        } else {
            *(float4*)&Bs[nk][nc] = *(const float4*)(Bp + (k0 + nk) * ldb + nc);
        }
        __syncthreads();
        #pragma unroll
        for (int kk = 0; kk < 16; kk++) {
            float4 a4 = *(const float4*)&As[kk][ty << 2];
            float4 b4 = *(const float4*)&Bs[kk][tx << 2];
            float aa[4] = {a4.x, a4.y, a4.z, a4.w};
            float bb[4] = {b4.x, b4.y, b4.z, b4.w};
            #pragma unroll
            for (int i = 0; i < 4; i++)
                #pragma unroll
                for (int j = 0; j < 4; j++)
                    acc[i][j] += aa[i] * bb[j];
        }
    }
    #pragma unroll
    for (int i = 0; i < 4; i++) {
        int r = (ty << 2) + i;
        #pragma unroll
        for (int j = 0; j < 4; j++) {
            int c = (tx << 2) + j;
            float v = acc[i][j];
            if (bias) v += bias[c];
            if (EPI >= 1) v = fmaxf(v, 0.0f);
            C[r * ldc + c] = v;
        }
    }
}

__global__ void __launch_bounds__(256) k_ao(const float* __restrict__ Wv,
                                            const float* __restrict__ bv)
{
    int m = blockIdx.z >> 3, h = blockIdx.z & 7;
    gemm64<false, 0>(g_wv + (m * H_ + h) * D_, MH_ * D_,
                     Wv + m * D_ * D_ + h * HD_, D_,
                     g_ao + m * B_ * D_ + h * HD_, D_, D_, bv + m * D_ + h * HD_);
}

__global__ void __launch_bounds__(256) k_softmax(const float* __restrict__ bk)
{
    int row = blockIdx.x * 8 + (threadIdx.x >> 5);
    int lane = threadIdx.x & 31;
    int b = row >> 6, mh = row & 63;
    int m = mh >> 3, h = mh & 7;
    const float* qp  = g_q + m * B_ * D_ + b * D_ + h * HD_;
    const float* bkp = bk + m * D_ + h * HD_;
    float bias = qp[lane] * bkp[lane] + qp[lane + 32] * bkp[lane + 32];
    #pragma unroll
    for (int o = 16; o; o >>= 1) bias += __shfl_xor_sync(0xffffffffu, bias, o);
    float* wrow = g_w + b * MH_ * S_ + mh * S_;
    float v[4], mx = -INFINITY;
    #pragma unroll
    for (int i = 0; i < 4; i++) {
        v[i] = (wrow[lane + 32 * i] + bias) * 0.125f;
        mx = fmaxf(mx, v[i]);
    }
    #pragma unroll
    for (int o = 16; o; o >>= 1) mx = fmaxf(mx, __shfl_xor_sync(0xffffffffu, mx, o));
    float sum = 0.0f;
    #pragma unroll
    for (int i = 0; i < 4; i++) { v[i] = __expf(v[i] - mx); sum += v[i]; }
    #pragma unroll
    for (int o = 16; o; o >>= 1) sum += __shfl_xor_sync(0xffffffffu, sum, o);
    float inv = 1.0f / sum;
    #pragma unroll
    for (int i = 0; i < 4; i++) wrow[lane + 32 * i] = v[i] * inv;
}

__global__ void __launch_bounds__(256) k_xfill(const float* __restrict__ ps)
{
    int i = blockIdx.x * 256 + threadIdx.x;
    if (i < M_ * B_ * D_) {
        int mb = i >> 9, d = i & (D_ - 1);
        g_x[mb * TWOD_ + D_ + d] = fmaxf(ps[i], 0.0f);
    }
}

__global__ void __launch_bounds__(128) k_final(const float* __restrict__ Wg2,
                                               const float* __restrict__ bg2,
                                               const float* __restrict__ pq,
                                               const float* __restrict__ pk,
                                               const float* __restrict__ pv,
                                               const float* __restrict__ ps,
                                               float* __restrict__ out)
{
    int z = blockIdx.x;
    int g = z >> 9, rem = z & 511;
    int m = rem >> 6, b = rem & 63;
    int gm = g * M_ + m;
    int tid = threadIdx.x, lane = tid & 31;
    const float* hg = g_hg + ((long)gm * B_ + b) * FF_;
    const float* wg = Wg2 + (long)gm * FF_;
    float s = 0.0f;
    for (int f = tid; f < FF_; f += 128) s += hg[f] * wg[f];
    #pragma unroll
    for (int o = 16; o; o >>= 1) s += __shfl_xor_sync(0xffffffffu, s, o);
    __shared__ float red[4];
    if (lane == 0) red[tid >> 5] = s;
    __syncthreads();
    float tot = red[0] + red[1] + red[2] + red[3];
    float gate = 1.0f / (1.0f + __expf(-(tot + bg2[gm])));
    const float* prevs[4] = {pq, pk, pv, ps};
    const float* pr = prevs[g] + ((long)m * B_ + b) * D_;
    const float* ob = g_o + ((long)gm * B_ + b) * D_;
    float* dst = out + (((long)((g + 1) & 3) * M_ + m) * B_ + b) * D_;
    for (int d = tid; d < D_; d += 128)
        dst[d] = gate * ob[d] + (1.0f - gate) * pr[d];
}

// ---------------- launch ----------------
extern "C" void kernel_launch(void* const* d_in, const int* in_sizes, int n_in,
                              void* d_out, int out_size)
{
    const float* prev_state = (const float*)d_in[0];
    const float* prev_query = (const float*)d_in[1];
    const float* prev_key   = (const float*)d_in[2];
    const float* prev_value = (const float*)d_in[3];
    const float* key_in     = (const float*)d_in[4];
    const float* value_in   = (const float*)d_in[5];
    const float* Wq  = (const float*)d_in[6];
    const float* bq  = (const float*)d_in[7];
    const float* Wk  = (const float*)d_in[8];
    const float* bk  = (const float*)d_in[9];
    const float* Wv  = (const float*)d_in[10];
    const float* bv  = (const float*)d_in[11];
    const float* Wo  = (const float*)d_in[12];
    const float* bo  = (const float*)d_in[13];
    const float* W1  = (const float*)d_in[14];
    const float* b1  = (const float*)d_in[15];
    const float* W2  = (const float*)d_in[16];
    const float* b2  = (const float*)d_in[17];
    const float* Wg1 = (const float*)d_in[18];
    const float* bg1 = (const float*)d_in[19];
    const float* Wg2 = (const float*)d_in[20];
    const float* bg2 = (const float*)d_in[21];
    float* out = (float*)d_out;

    h_qproj  <<<dim3(4, 1, M_),            256>>>(prev_query, Wq, bq);
    h_qk     <<<dim3(4, 1, M_ * H_),       256>>>(Wk);
    h_scores <<<dim3(1, 1, B_),            256>>>(key_in);
    k_softmax<<<(B_ * MH_) / 8,            256>>>(bk);
    h_wv     <<<dim3(4, 1, B_),            256>>>(value_in);
    k_ao     <<<dim3(1, 1, M_ * H_),       256>>>(Wv, bv);
    h_attnout<<<dim3(4, 1, M_),            256>>>(Wo, bo);
    k_xfill  <<<(M_ * B_ * D_ + 255) / 256, 256>>>(prev_state);
    k_mlp1   <<<dim3(FF_ / 128, 1, 64),    256>>>(W1, b1, Wg1, bg1);
    k_mlp2   <<<dim3(D_ / 128, 1, 32),     256>>>(W2, b2);
    k_final  <<<4 * M_ * B_, 128>>>(Wg2, bg2, prev_query, prev_key,
                                    prev_value, prev_state, out);
}